// round 1
// baseline (speedup 1.0000x reference)
#include <cuda_runtime.h>
#include <math.h>

#define NN 200000
#define NE 3200000
#define NG 1000
#define NF 128
#define KP 30
#define CC 97

// ---------------- device scratch (no allocations allowed) ----------------
__device__ __align__(16) float g_deg[NN];
__device__ __align__(16) float g_invsqrt[NN];
__device__ __align__(16) float g_invdeg[NN];
__device__ __align__(16) float g_coef[NE];
__device__ __align__(16) float g_hw[NN * 32];
__device__ __align__(16) float g_hw4[NN];
__device__ __align__(16) float g_x1[NN * 32];
__device__ __align__(16) float g_x2[NN * 32];
__device__ __align__(16) float g_x3[NN * 32];
__device__ __align__(16) float g_x4[NN];
__device__ int g_cnt[NG];
__device__ int g_start[NG];

// ---------------- init ----------------
__global__ void k_init() {
    int i = blockIdx.x * blockDim.x + threadIdx.x;
    if (i < NN) g_deg[i] = 0.f;
    if (i < NG) g_cnt[i] = 0;
}

__global__ void k_deg(const int* __restrict__ ei) {
    int e = blockIdx.x * blockDim.x + threadIdx.x;
    if (e >= NE) return;
    int s = ei[e], d = ei[NE + e];
    if (s != d) atomicAdd(&g_deg[d], 1.0f);
}

__global__ void k_prep(const int* __restrict__ batch) {
    int i = blockIdx.x * blockDim.x + threadIdx.x;
    if (i >= NN) return;
    float dg = g_deg[i] + 1.0f;
    g_invsqrt[i] = rsqrtf(dg);
    g_invdeg[i]  = 1.0f / dg;
    atomicAdd(&g_cnt[batch[i]], 1);
}

__global__ void k_coef(const int* __restrict__ ei) {
    int e = blockIdx.x * blockDim.x + threadIdx.x;
    if (e >= NE) return;
    int s = ei[e], d = ei[NE + e];
    g_coef[e] = (s != d) ? g_invsqrt[s] * g_invsqrt[d] : 0.0f;
}

__global__ void k_scan() {
    if (threadIdx.x == 0) {
        int acc = 0;
        for (int g = 0; g < NG; g++) { g_start[g] = acc; acc += g_cnt[g]; }
    }
}

// ---------------- GEMM: hw = h @ W ; out = hw*inv_deg + b (self-loop init) ----
template <int KDIM>
__global__ void k_gemm32(const float* __restrict__ h, const float* __restrict__ W,
                         const float* __restrict__ b,
                         float* __restrict__ hw, float* __restrict__ out) {
    __shared__ float sW[KDIM * 32];
    __shared__ float sb[32];
    for (int i = threadIdx.x; i < KDIM * 32; i += blockDim.x) sW[i] = W[i];
    if (threadIdx.x < 32) sb[threadIdx.x] = b[threadIdx.x];
    __syncthreads();
    int node = blockIdx.x * blockDim.x + threadIdx.x;
    if (node >= NN) return;
    float acc[32];
#pragma unroll
    for (int j = 0; j < 32; j++) acc[j] = 0.f;
    const float4* hr = (const float4*)(h + (size_t)node * KDIM);
    for (int k4 = 0; k4 < KDIM / 4; k4++) {
        float4 v = hr[k4];
        const float* w0 = &sW[(k4 * 4) * 32];
#pragma unroll
        for (int j = 0; j < 32; j++)
            acc[j] += v.x * w0[j] + v.y * w0[32 + j] + v.z * w0[64 + j] + v.w * w0[96 + j];
    }
    float idg = g_invdeg[node];
    float4* hwv = (float4*)(hw + (size_t)node * 32);
    float4* ov  = (float4*)(out + (size_t)node * 32);
#pragma unroll
    for (int q = 0; q < 8; q++) {
        float4 a;
        a.x = acc[4 * q]; a.y = acc[4 * q + 1]; a.z = acc[4 * q + 2]; a.w = acc[4 * q + 3];
        hwv[q] = a;
        float4 o;
        o.x = a.x * idg + sb[4 * q];     o.y = a.y * idg + sb[4 * q + 1];
        o.z = a.z * idg + sb[4 * q + 2]; o.w = a.w * idg + sb[4 * q + 3];
        ov[q] = o;
    }
}

// layer 4: 32 -> 1
__global__ void k_gemm_c1(const float* __restrict__ h, const float* __restrict__ W,
                          const float* __restrict__ b) {
    __shared__ float sW[32];
    __shared__ float sb0;
    if (threadIdx.x < 32) sW[threadIdx.x] = W[threadIdx.x];
    if (threadIdx.x == 0) sb0 = b[0];
    __syncthreads();
    int node = blockIdx.x * blockDim.x + threadIdx.x;
    if (node >= NN) return;
    const float4* hr = (const float4*)(h + (size_t)node * 32);
    float acc = 0.f;
#pragma unroll
    for (int q = 0; q < 8; q++) {
        float4 v = hr[q];
        acc += v.x * sW[4 * q] + v.y * sW[4 * q + 1] + v.z * sW[4 * q + 2] + v.w * sW[4 * q + 3];
    }
    g_hw4[node] = acc;
    g_x4[node] = acc * g_invdeg[node] + sb0;
}

// ---------------- edge scatter: out[dst] += hw[src] * coef (vector red) ------
__global__ void k_scatter32(const int* __restrict__ ei,
                            const float* __restrict__ hw, float* __restrict__ out) {
    int e = blockIdx.x * blockDim.x + threadIdx.x;
    if (e >= NE) return;
    float c = g_coef[e];
    if (c == 0.0f) return;
    int s = ei[e], d = ei[NE + e];
    const float4* src = (const float4*)(hw + (size_t)s * 32);
    float* dst = out + (size_t)d * 32;
#pragma unroll
    for (int q = 0; q < 8; q++) {
        float4 v = src[q];
        v.x *= c; v.y *= c; v.z *= c; v.w *= c;
        asm volatile("red.global.add.v4.f32 [%0], {%1,%2,%3,%4};"
                     :: "l"(dst + 4 * q), "f"(v.x), "f"(v.y), "f"(v.z), "f"(v.w)
                     : "memory");
    }
}

__global__ void k_scatter1(const int* __restrict__ ei) {
    int e = blockIdx.x * blockDim.x + threadIdx.x;
    if (e >= NE) return;
    float c = g_coef[e];
    if (c == 0.0f) return;
    int s = ei[e], d = ei[NE + e];
    atomicAdd(&g_x4[d], g_hw4[s] * c);
}

// ---------------- tanh ----------------
__global__ void k_tanh4(float* __restrict__ buf, int n4) {
    int i = blockIdx.x * blockDim.x + threadIdx.x;
    if (i >= n4) return;
    float4* p = (float4*)buf;
    float4 v = p[i];
    v.x = tanhf(v.x); v.y = tanhf(v.y); v.z = tanhf(v.z); v.w = tanhf(v.w);
    p[i] = v;
}

__global__ void k_tanh1(int n) {
    int i = blockIdx.x * blockDim.x + threadIdx.x;
    if (i >= n) return;
    g_x4[i] = tanhf(g_x4[i]);
}

// ---------------- sort-pool (top-K by x4 desc, index asc) + CNN/FC head ------
__global__ void __launch_bounds__(128) k_head(
    const float* __restrict__ w5, const float* __restrict__ b5,
    const float* __restrict__ w6, const float* __restrict__ b6,
    const float* __restrict__ fw1, const float* __restrict__ fb1,
    const float* __restrict__ fw2, const float* __restrict__ fb2,
    float* __restrict__ out) {
    const int T = 128;
    int g = blockIdx.x;
    int tid = threadIdx.x;

    __shared__ float pooled[KP * CC];   // 30 x 97
    __shared__ float z5[16 * 30];
    __shared__ float p5[16 * 15];
    __shared__ float z6[352];
    __shared__ float h1[128];
    __shared__ float logits[10];
    __shared__ float bestv[128];
    __shared__ int   besti[128];
    __shared__ float pv;
    __shared__ int   pidx;

    int start = g_start[g];
    int cnt   = g_cnt[g];
    int kk = cnt < KP ? cnt : KP;

    for (int i = tid; i < KP * CC; i += T) pooled[i] = 0.f;
    if (tid == 0) { pv = 3.0e38f; pidx = -1; }
    __syncthreads();

    for (int r = 0; r < kk; r++) {
        float lpv = pv; int lpidx = pidx;
        float bv = -3.0e38f; int bi = 0x7fffffff;
        for (int i = start + tid; i < start + cnt; i += T) {
            float v = g_x4[i];
            // strictly after previous selection in (value desc, index asc) order
            bool after = (v < lpv) || (v == lpv && i > lpidx);
            if (after && ((v > bv) || (v == bv && i < bi))) { bv = v; bi = i; }
        }
        bestv[tid] = bv; besti[tid] = bi;
        __syncthreads();
        for (int sft = T / 2; sft > 0; sft >>= 1) {
            if (tid < sft) {
                float ov = bestv[tid + sft]; int oi = besti[tid + sft];
                if ((ov > bestv[tid]) || (ov == bestv[tid] && oi < besti[tid])) {
                    bestv[tid] = ov; besti[tid] = oi;
                }
            }
            __syncthreads();
        }
        int node = besti[0];
        for (int c = tid; c < CC; c += T) {
            float val;
            if (c < 32)      val = g_x1[(size_t)node * 32 + c];
            else if (c < 64) val = g_x2[(size_t)node * 32 + (c - 32)];
            else if (c < 96) val = g_x3[(size_t)node * 32 + (c - 64)];
            else             val = g_x4[node];
            pooled[r * CC + c] = val;
        }
        if (tid == 0) { pv = bestv[0]; pidx = node; }
        __syncthreads();
    }

    // conv5: kernel 97, stride 97 -> per-position linear [16 x 30], relu
    for (int idx = tid; idx < 16 * 30; idx += T) {
        int oc = idx / 30, t = idx % 30;
        float s = b5[oc];
        const float* wr = &w5[oc * 97];
        const float* pr = &pooled[t * 97];
        for (int c = 0; c < 97; c++) s += pr[c] * wr[c];
        z5[oc * 30 + t] = fmaxf(s, 0.f);
    }
    __syncthreads();
    // maxpool(2,2) -> [16 x 15]
    for (int idx = tid; idx < 16 * 15; idx += T) {
        int oc = idx / 15, u = idx % 15;
        p5[idx] = fmaxf(z5[oc * 30 + 2 * u], z5[oc * 30 + 2 * u + 1]);
    }
    __syncthreads();
    // conv6: 16->32, k=5 -> [32 x 11], relu (flatten order oc*11+v)
    for (int idx = tid; idx < 352; idx += T) {
        int oc = idx / 11, v = idx % 11;
        float s = b6[oc];
        for (int ic = 0; ic < 16; ic++) {
            const float* wr = &w6[oc * 80 + ic * 5];
            const float* pr = &p5[ic * 15 + v];
#pragma unroll
            for (int q = 0; q < 5; q++) s += pr[q] * wr[q];
        }
        z6[idx] = fmaxf(s, 0.f);
    }
    __syncthreads();
    // fc1: 352 -> 128, relu
    for (int j = tid; j < 128; j += T) {
        float s = fb1[j];
        for (int i = 0; i < 352; i++) s += z6[i] * fw1[i * 128 + j];
        h1[j] = fmaxf(s, 0.f);
    }
    __syncthreads();
    // fc2: 128 -> 10
    for (int c = tid; c < 10; c += T) {
        float s = fb2[c];
        for (int j = 0; j < 128; j++) s += h1[j] * fw2[j * 10 + c];
        logits[c] = s;
    }
    __syncthreads();
    if (tid == 0) {
        float mx = logits[0];
        for (int c = 1; c < 10; c++) mx = fmaxf(mx, logits[c]);
        float se = 0.f;
        for (int c = 0; c < 10; c++) se += expf(logits[c] - mx);
        float lse = logf(se) + mx;
        for (int c = 0; c < 10; c++) out[(size_t)g * 10 + c] = logits[c] - lse;
    }
}

// ---------------- launch ----------------
extern "C" void kernel_launch(void* const* d_in, const int* in_sizes, int n_in,
                              void* d_out, int out_size) {
    const float* x      = (const float*)d_in[0];
    const int*   ei     = (const int*)d_in[1];
    const int*   batch  = (const int*)d_in[2];
    const float* W1 = (const float*)d_in[3];  const float* b1 = (const float*)d_in[4];
    const float* W2 = (const float*)d_in[5];  const float* b2 = (const float*)d_in[6];
    const float* W3 = (const float*)d_in[7];  const float* b3 = (const float*)d_in[8];
    const float* W4 = (const float*)d_in[9];  const float* b4 = (const float*)d_in[10];
    const float* w5 = (const float*)d_in[11]; const float* b5 = (const float*)d_in[12];
    const float* w6 = (const float*)d_in[13]; const float* b6 = (const float*)d_in[14];
    const float* fw1 = (const float*)d_in[15]; const float* fb1 = (const float*)d_in[16];
    const float* fw2 = (const float*)d_in[17]; const float* fb2 = (const float*)d_in[18];
    float* out = (float*)d_out;

    void *p_hw, *p_hw4, *p_x1, *p_x2, *p_x3, *p_x4;
    cudaGetSymbolAddress(&p_hw, g_hw);
    cudaGetSymbolAddress(&p_hw4, g_hw4);
    cudaGetSymbolAddress(&p_x1, g_x1);
    cudaGetSymbolAddress(&p_x2, g_x2);
    cudaGetSymbolAddress(&p_x3, g_x3);
    cudaGetSymbolAddress(&p_x4, g_x4);
    float* hw = (float*)p_hw;
    float* x1 = (float*)p_x1;
    float* x2 = (float*)p_x2;
    float* x3 = (float*)p_x3;

    const int TB = 256;
    const int NB_N = (NN + TB - 1) / TB;
    const int NB_E = (NE + TB - 1) / TB;
    const int N4   = NN * 32 / 4;
    const int NB_T = (N4 + TB - 1) / TB;

    k_init<<<NB_N, TB>>>();
    k_deg<<<NB_E, TB>>>(ei);
    k_prep<<<NB_N, TB>>>(batch);
    k_coef<<<NB_E, TB>>>(ei);
    k_scan<<<1, 32>>>();

    // layer 1: 128 -> 32
    k_gemm32<128><<<NB_N, TB>>>(x, W1, b1, hw, x1);
    k_scatter32<<<NB_E, TB>>>(ei, hw, x1);
    k_tanh4<<<NB_T, TB>>>(x1, N4);

    // layer 2: 32 -> 32
    k_gemm32<32><<<NB_N, TB>>>(x1, W2, b2, hw, x2);
    k_scatter32<<<NB_E, TB>>>(ei, hw, x2);
    k_tanh4<<<NB_T, TB>>>(x2, N4);

    // layer 3: 32 -> 32
    k_gemm32<32><<<NB_N, TB>>>(x2, W3, b3, hw, x3);
    k_scatter32<<<NB_E, TB>>>(ei, hw, x3);
    k_tanh4<<<NB_T, TB>>>(x3, N4);

    // layer 4: 32 -> 1
    k_gemm_c1<<<NB_N, TB>>>(x3, W4, b4);
    k_scatter1<<<NB_E, TB>>>(ei);
    k_tanh1<<<NB_N, TB>>>(NN);

    // sort-pool + head
    k_head<<<NG, 128>>>(w5, b5, w6, b6, fw1, fb1, fw2, fb2, out);
}

// round 2
// speedup vs baseline: 1.7421x; 1.7421x over previous
#include <cuda_runtime.h>
#include <math.h>

#define NN 200000
#define NE 3200000
#define NG 1000
#define KP 30
#define CC 97
#define NBN 782            // ceil(NN/256)
#define MAXSORT 2048

// ---------------- device scratch ----------------
__device__ int   g_deg[NN];
__device__ float g_invsqrt[NN];
__device__ float g_invdeg[NN];
__device__ int   g_bsum[NBN];
__device__ int   g_bofs[NBN];
__device__ int   g_rowstart[NN];
__device__ int   g_cursor[NN];
__device__ long long g_epack[NE];        // [coef_bits:32 | src:32]
__device__ __align__(16) float g_hw[NN * 32];
__device__ __align__(16) float g_hw4[NN];
__device__ __align__(16) float g_x1[NN * 32];
__device__ __align__(16) float g_x2[NN * 32];
__device__ __align__(16) float g_x3[NN * 32];
__device__ __align__(16) float g_x4[NN];
__device__ int g_cnt[NG];
__device__ int g_start[NG];

// ---------------- preprocessing ----------------
__global__ void k_init() {
    int i = blockIdx.x * blockDim.x + threadIdx.x;
    if (i < NN) g_deg[i] = 0;
    if (i < NG) g_cnt[i] = 0;
}

// degree count (non-self edges) + per-graph node count
__global__ void k_degcnt(const int* __restrict__ ei, const int* __restrict__ batch) {
    int i = blockIdx.x * blockDim.x + threadIdx.x;
    if (i < NE) {
        int s = ei[i], d = ei[NE + i];
        if (s != d) atomicAdd(&g_deg[d], 1);
    }
    if (i < NN) atomicAdd(&g_cnt[batch[i]], 1);
}

// inv_sqrt / inv_deg + per-block degree sums (for row-pointer scan)
__global__ void k_prep() {
    __shared__ int ssum[256];
    int t = threadIdx.x;
    int i = blockIdx.x * 256 + t;
    int d = 0;
    if (i < NN) {
        d = g_deg[i];
        float dg = (float)d + 1.0f;
        g_invsqrt[i] = rsqrtf(dg);
        g_invdeg[i]  = 1.0f / dg;
    }
    ssum[t] = d;
    __syncthreads();
    for (int s = 128; s > 0; s >>= 1) {
        if (t < s) ssum[t] += ssum[t + s];
        __syncthreads();
    }
    if (t == 0) g_bsum[blockIdx.x] = ssum[0];
}

// single-block scans: block sums -> block offsets, graph counts -> graph starts
__global__ void k_scan1() {
    __shared__ int sh[1024];
    int t = threadIdx.x;
    // scan 1: block sums (NBN = 782)
    sh[t] = (t < NBN) ? g_bsum[t] : 0;
    __syncthreads();
    for (int off = 1; off < 1024; off <<= 1) {
        int v = (t >= off) ? sh[t - off] : 0;
        __syncthreads();
        sh[t] += v;
        __syncthreads();
    }
    if (t < NBN) g_bofs[t] = sh[t] - g_bsum[t];   // exclusive
    __syncthreads();
    // scan 2: graph counts (NG = 1000)
    int c = (t < NG) ? g_cnt[t] : 0;
    sh[t] = c;
    __syncthreads();
    for (int off = 1; off < 1024; off <<= 1) {
        int v = (t >= off) ? sh[t - off] : 0;
        __syncthreads();
        sh[t] += v;
        __syncthreads();
    }
    if (t < NG) g_start[t] = sh[t] - c;           // exclusive
}

// per-node row start = block offset + in-block exclusive scan of degrees
__global__ void k_rowfill() {
    __shared__ int sh[256];
    int t = threadIdx.x;
    int i = blockIdx.x * 256 + t;
    int d = (i < NN) ? g_deg[i] : 0;
    sh[t] = d;
    __syncthreads();
    for (int off = 1; off < 256; off <<= 1) {
        int v = (t >= off) ? sh[t - off] : 0;
        __syncthreads();
        sh[t] += v;
        __syncthreads();
    }
    if (i < NN) {
        int rs = g_bofs[blockIdx.x] + sh[t] - d;
        g_rowstart[i] = rs;
        g_cursor[i]   = rs;
    }
}

// scatter edges into CSR buckets with packed (coef, src)
__global__ void k_fill(const int* __restrict__ ei) {
    int e = blockIdx.x * blockDim.x + threadIdx.x;
    if (e >= NE) return;
    int s = ei[e], d = ei[NE + e];
    if (s == d) return;
    float c = g_invsqrt[s] * g_invsqrt[d];
    int pos = atomicAdd(&g_cursor[d], 1);
    g_epack[pos] = ((long long)__float_as_int(c) << 32) | (unsigned int)s;
}

// ---------------- GEMM: hw = h @ W (weights in SMEM, float4 LDS) ----------------
template <int KDIM>
__global__ void k_gemm32(const float* __restrict__ h, const float* __restrict__ W,
                         float* __restrict__ hw) {
    __shared__ float sW[KDIM * 32];
    for (int i = threadIdx.x; i < KDIM * 32; i += blockDim.x) sW[i] = W[i];
    __syncthreads();
    int node = blockIdx.x * blockDim.x + threadIdx.x;
    if (node >= NN) return;
    float acc[32];
#pragma unroll
    for (int j = 0; j < 32; j++) acc[j] = 0.f;
    const float4* hr = (const float4*)(h + (size_t)node * KDIM);
#pragma unroll 4
    for (int k4 = 0; k4 < KDIM / 4; k4++) {
        float4 v = hr[k4];
        const float* hk = &v.x;
#pragma unroll
        for (int kk = 0; kk < 4; kk++) {
            float hv = hk[kk];
            const float4* wr = (const float4*)&sW[(k4 * 4 + kk) * 32];
#pragma unroll
            for (int q = 0; q < 8; q++) {
                float4 w = wr[q];
                acc[4 * q]     += hv * w.x;
                acc[4 * q + 1] += hv * w.y;
                acc[4 * q + 2] += hv * w.z;
                acc[4 * q + 3] += hv * w.w;
            }
        }
    }
    float4* hwv = (float4*)(hw + (size_t)node * 32);
#pragma unroll
    for (int q = 0; q < 8; q++) {
        float4 a;
        a.x = acc[4 * q]; a.y = acc[4 * q + 1]; a.z = acc[4 * q + 2]; a.w = acc[4 * q + 3];
        hwv[q] = a;
    }
}

// layer 4 projection: hw4 = h @ W4   (32 -> 1)
__global__ void k_gemm_c1(const float* __restrict__ h, const float* __restrict__ W) {
    __shared__ float sW[32];
    if (threadIdx.x < 32) sW[threadIdx.x] = W[threadIdx.x];
    __syncthreads();
    int node = blockIdx.x * blockDim.x + threadIdx.x;
    if (node >= NN) return;
    const float4* hr = (const float4*)(h + (size_t)node * 32);
    float acc = 0.f;
#pragma unroll
    for (int q = 0; q < 8; q++) {
        float4 v = hr[q];
        acc += v.x * sW[4 * q] + v.y * sW[4 * q + 1] + v.z * sW[4 * q + 2] + v.w * sW[4 * q + 3];
    }
    g_hw4[node] = acc;
}

// ---------------- CSR gather: out = tanh(sum coef*hw[src] + hw[node]*invdeg + b) --
__global__ void k_gather32(const float* __restrict__ hw, float* __restrict__ out,
                           const float* __restrict__ b) {
    int gtid = blockIdx.x * blockDim.x + threadIdx.x;
    int node = gtid >> 5;
    if (node >= NN) return;
    int lane = threadIdx.x & 31;
    int rs = g_rowstart[node];
    int re = rs + g_deg[node];
    float acc = hw[(size_t)node * 32 + lane] * g_invdeg[node] + __ldg(&b[lane]);
    int e = rs;
    for (; e + 1 < re; e += 2) {
        long long p0 = __ldg(&g_epack[e]);
        long long p1 = __ldg(&g_epack[e + 1]);
        int s0 = (int)(p0 & 0xffffffffLL);
        int s1 = (int)(p1 & 0xffffffffLL);
        float c0 = __int_as_float((int)(p0 >> 32));
        float c1 = __int_as_float((int)(p1 >> 32));
        float v0 = __ldg(&hw[(size_t)s0 * 32 + lane]);
        float v1 = __ldg(&hw[(size_t)s1 * 32 + lane]);
        acc += v0 * c0 + v1 * c1;
    }
    if (e < re) {
        long long p = __ldg(&g_epack[e]);
        int s = (int)(p & 0xffffffffLL);
        float c = __int_as_float((int)(p >> 32));
        acc += __ldg(&hw[(size_t)s * 32 + lane]) * c;
    }
    out[(size_t)node * 32 + lane] = tanhf(acc);
}

__global__ void k_gather1(const float* __restrict__ b4) {
    int node = blockIdx.x * blockDim.x + threadIdx.x;
    if (node >= NN) return;
    int rs = g_rowstart[node];
    int re = rs + g_deg[node];
    float acc = g_hw4[node] * g_invdeg[node] + __ldg(&b4[0]);
    int e = rs;
    for (; e + 1 < re; e += 2) {
        long long p0 = __ldg(&g_epack[e]);
        long long p1 = __ldg(&g_epack[e + 1]);
        int s0 = (int)(p0 & 0xffffffffLL);
        int s1 = (int)(p1 & 0xffffffffLL);
        float c0 = __int_as_float((int)(p0 >> 32));
        float c1 = __int_as_float((int)(p1 >> 32));
        acc += g_hw4[s0] * c0 + g_hw4[s1] * c1;
    }
    if (e < re) {
        long long p = __ldg(&g_epack[e]);
        int s = (int)(p & 0xffffffffLL);
        acc += g_hw4[s] * __int_as_float((int)(p >> 32));
    }
    g_x4[node] = tanhf(acc);
}

// ---------------- sort-pool + CNN/FC head ----------------
__global__ void __launch_bounds__(128) k_head(
    const float* __restrict__ w5, const float* __restrict__ b5,
    const float* __restrict__ w6, const float* __restrict__ b6,
    const float* __restrict__ fw1, const float* __restrict__ fb1,
    const float* __restrict__ fw2, const float* __restrict__ fb2,
    float* __restrict__ out) {
    const int T = 128;
    int g = blockIdx.x;
    int tid = threadIdx.x;

    __shared__ unsigned long long keys[MAXSORT];
    __shared__ float pooled[KP * CC];
    __shared__ float z5[16 * 30];
    __shared__ float p5[16 * 15];
    __shared__ float z6[352];
    __shared__ float h1[128];
    __shared__ float logits[10];
    __shared__ int   seln[KP];
    __shared__ float bestv[128];
    __shared__ int   besti[128];

    int start = g_start[g];
    int cnt   = g_cnt[g];
    int kk = cnt < KP ? cnt : KP;

    for (int i = tid; i < KP * CC; i += T) pooled[i] = 0.f;

    if (cnt <= MAXSORT) {
        int n2 = 1;
        while (n2 < cnt) n2 <<= 1;
        for (int i = tid; i < n2; i += T) {
            if (i < cnt) {
                unsigned u = __float_as_uint(g_x4[start + i]);
                u ^= (u >> 31) ? 0xFFFFFFFFu : 0x80000000u;  // ascending order bits
                u = ~u;                                       // descending
                keys[i] = ((unsigned long long)u << 32) | (unsigned)(start + i);
            } else {
                keys[i] = 0xFFFFFFFFFFFFFFFFull;
            }
        }
        __syncthreads();
        for (int k = 2; k <= n2; k <<= 1) {
            for (int j = k >> 1; j > 0; j >>= 1) {
                for (int i = tid; i < n2; i += T) {
                    int ixj = i ^ j;
                    if (ixj > i) {
                        bool up = ((i & k) == 0);
                        unsigned long long a = keys[i], bk = keys[ixj];
                        if ((a > bk) == up) { keys[i] = bk; keys[ixj] = a; }
                    }
                }
                __syncthreads();
            }
        }
        for (int r = tid; r < kk; r += T)
            seln[r] = (int)(keys[r] & 0xffffffffull);
        __syncthreads();
    } else {
        // fallback: iterative selection (value desc, index asc)
        __shared__ float pv_s;
        __shared__ int pidx_s;
        if (tid == 0) { pv_s = 3.0e38f; pidx_s = -1; }
        __syncthreads();
        for (int r = 0; r < kk; r++) {
            float lpv = pv_s; int lpidx = pidx_s;
            float bv = -3.0e38f; int bi = 0x7fffffff;
            for (int i = start + tid; i < start + cnt; i += T) {
                float v = g_x4[i];
                bool after = (v < lpv) || (v == lpv && i > lpidx);
                if (after && ((v > bv) || (v == bv && i < bi))) { bv = v; bi = i; }
            }
            bestv[tid] = bv; besti[tid] = bi;
            __syncthreads();
            for (int sft = T / 2; sft > 0; sft >>= 1) {
                if (tid < sft) {
                    float ov = bestv[tid + sft]; int oi = besti[tid + sft];
                    if ((ov > bestv[tid]) || (ov == bestv[tid] && oi < besti[tid])) {
                        bestv[tid] = ov; besti[tid] = oi;
                    }
                }
                __syncthreads();
            }
            if (tid == 0) { seln[r] = besti[0]; pv_s = bestv[0]; pidx_s = besti[0]; }
            __syncthreads();
        }
    }

    // gather pooled rows [kk x 97]
    for (int idx = tid; idx < kk * CC; idx += T) {
        int r = idx / CC, c = idx % CC;
        int node = seln[r];
        float val;
        if (c < 32)      val = g_x1[(size_t)node * 32 + c];
        else if (c < 64) val = g_x2[(size_t)node * 32 + (c - 32)];
        else if (c < 96) val = g_x3[(size_t)node * 32 + (c - 64)];
        else             val = g_x4[node];
        pooled[r * CC + c] = val;
    }
    __syncthreads();

    // conv5 (k=97, s=97) + relu -> [16 x 30]
    for (int idx = tid; idx < 16 * 30; idx += T) {
        int oc = idx / 30, t = idx % 30;
        float s = b5[oc];
        const float* wr = &w5[oc * 97];
        const float* pr = &pooled[t * 97];
        for (int c = 0; c < 97; c++) s += pr[c] * wr[c];
        z5[oc * 30 + t] = fmaxf(s, 0.f);
    }
    __syncthreads();
    // maxpool(2,2) -> [16 x 15]
    for (int idx = tid; idx < 16 * 15; idx += T) {
        int oc = idx / 15, u = idx % 15;
        p5[idx] = fmaxf(z5[oc * 30 + 2 * u], z5[oc * 30 + 2 * u + 1]);
    }
    __syncthreads();
    // conv6 (16->32, k=5) + relu -> [32 x 11]
    for (int idx = tid; idx < 352; idx += T) {
        int oc = idx / 11, v = idx % 11;
        float s = b6[oc];
        for (int ic = 0; ic < 16; ic++) {
            const float* wr = &w6[oc * 80 + ic * 5];
            const float* pr = &p5[ic * 15 + v];
#pragma unroll
            for (int q = 0; q < 5; q++) s += pr[q] * wr[q];
        }
        z6[idx] = fmaxf(s, 0.f);
    }
    __syncthreads();
    // fc1 (352 -> 128) + relu
    for (int j = tid; j < 128; j += T) {
        float s = fb1[j];
        for (int i = 0; i < 352; i++) s += z6[i] * fw1[i * 128 + j];
        h1[j] = fmaxf(s, 0.f);
    }
    __syncthreads();
    // fc2 (128 -> 10)
    for (int c = tid; c < 10; c += T) {
        float s = fb2[c];
        for (int j = 0; j < 128; j++) s += h1[j] * fw2[j * 10 + c];
        logits[c] = s;
    }
    __syncthreads();
    if (tid == 0) {
        float mx = logits[0];
        for (int c = 1; c < 10; c++) mx = fmaxf(mx, logits[c]);
        float se = 0.f;
        for (int c = 0; c < 10; c++) se += expf(logits[c] - mx);
        float lse = logf(se) + mx;
        for (int c = 0; c < 10; c++) out[(size_t)g * 10 + c] = logits[c] - lse;
    }
}

// ---------------- launch ----------------
extern "C" void kernel_launch(void* const* d_in, const int* in_sizes, int n_in,
                              void* d_out, int out_size) {
    const float* x      = (const float*)d_in[0];
    const int*   ei     = (const int*)d_in[1];
    const int*   batch  = (const int*)d_in[2];
    const float* W1 = (const float*)d_in[3];  const float* b1 = (const float*)d_in[4];
    const float* W2 = (const float*)d_in[5];  const float* b2 = (const float*)d_in[6];
    const float* W3 = (const float*)d_in[7];  const float* b3 = (const float*)d_in[8];
    const float* W4 = (const float*)d_in[9];  const float* b4 = (const float*)d_in[10];
    const float* w5 = (const float*)d_in[11]; const float* b5 = (const float*)d_in[12];
    const float* w6 = (const float*)d_in[13]; const float* b6 = (const float*)d_in[14];
    const float* fw1 = (const float*)d_in[15]; const float* fb1 = (const float*)d_in[16];
    const float* fw2 = (const float*)d_in[17]; const float* fb2 = (const float*)d_in[18];
    float* out = (float*)d_out;

    void *p_hw, *p_x1, *p_x2, *p_x3;
    cudaGetSymbolAddress(&p_hw, g_hw);
    cudaGetSymbolAddress(&p_x1, g_x1);
    cudaGetSymbolAddress(&p_x2, g_x2);
    cudaGetSymbolAddress(&p_x3, g_x3);
    float* hw = (float*)p_hw;
    float* x1 = (float*)p_x1;
    float* x2 = (float*)p_x2;
    float* x3 = (float*)p_x3;

    const int TB = 256;
    const int NB_N = NBN;                       // 782
    const int NB_E = (NE + TB - 1) / TB;
    const int NB_W = (NN * 32 + TB - 1) / TB;   // warp-per-node gather

    // CSR + normalization preprocessing
    k_init<<<NB_N, TB>>>();
    k_degcnt<<<NB_E, TB>>>(ei, batch);
    k_prep<<<NB_N, TB>>>();
    k_scan1<<<1, 1024>>>();
    k_rowfill<<<NB_N, TB>>>();
    k_fill<<<NB_E, TB>>>(ei);

    // layer 1: 128 -> 32
    k_gemm32<128><<<NB_N, TB>>>(x, W1, hw);
    k_gather32<<<NB_W, TB>>>(hw, x1, b1);
    // layer 2: 32 -> 32
    k_gemm32<32><<<NB_N, TB>>>(x1, W2, hw);
    k_gather32<<<NB_W, TB>>>(hw, x2, b2);
    // layer 3: 32 -> 32
    k_gemm32<32><<<NB_N, TB>>>(x2, W3, hw);
    k_gather32<<<NB_W, TB>>>(hw, x3, b3);
    // layer 4: 32 -> 1
    k_gemm_c1<<<NB_N, TB>>>(x3, W4);
    k_gather1<<<NB_N, TB>>>(b4);

    // sort-pool + head
    k_head<<<NG, 128>>>(w5, b5, w6, b6, fw1, fb1, fw2, fb2, out);
}

// round 3
// speedup vs baseline: 1.9139x; 1.0987x over previous
#include <cuda_runtime.h>
#include <math.h>

#define NN 200000
#define NE 3200000
#define NG 1000
#define KP 30
#define CC 97
#define NBN 782            // ceil(NN/256)
#define MAXSORT 2048
#define FULLM 0xffffffffu

// ---------------- device scratch ----------------
__device__ int   g_deg[NN];
__device__ float g_invsqrt[NN];
__device__ float g_invdeg[NN];
__device__ int   g_bsum[NBN];
__device__ int   g_bofs[NBN];
__device__ int   g_rowstart[NN];
__device__ int   g_cursor[NN];
__device__ long long g_epack[NE];        // [coef_bits:32 | src:32]
__device__ __align__(16) float g_hw[NN * 32];
__device__ __align__(16) float g_hw4[NN];
__device__ __align__(16) float g_x1[NN * 32];
__device__ __align__(16) float g_x2[NN * 32];
__device__ __align__(16) float g_x3[NN * 32];
__device__ __align__(16) float g_x4[NN];
__device__ int g_cnt[NG];
__device__ int g_start[NG];

// ---------------- preprocessing ----------------
__global__ void k_init() {
    int i = blockIdx.x * blockDim.x + threadIdx.x;
    if (i < NN) g_deg[i] = 0;
    if (i < NG) g_cnt[i] = 0;
}

__global__ void k_degcnt(const int* __restrict__ ei, const int* __restrict__ batch) {
    int i = blockIdx.x * blockDim.x + threadIdx.x;
    if (i < NE) {
        int s = __ldg(&ei[i]), d = __ldg(&ei[NE + i]);
        if (s != d) atomicAdd(&g_deg[d], 1);
    }
    if (i < NN) atomicAdd(&g_cnt[batch[i]], 1);
}

__global__ void k_prep() {
    __shared__ int ssum[256];
    int t = threadIdx.x;
    int i = blockIdx.x * 256 + t;
    int d = 0;
    if (i < NN) {
        d = g_deg[i];
        float dg = (float)d + 1.0f;
        g_invsqrt[i] = rsqrtf(dg);
        g_invdeg[i]  = 1.0f / dg;
    }
    ssum[t] = d;
    __syncthreads();
    for (int s = 128; s > 0; s >>= 1) {
        if (t < s) ssum[t] += ssum[t + s];
        __syncthreads();
    }
    if (t == 0) g_bsum[blockIdx.x] = ssum[0];
}

__global__ void k_scan1() {
    __shared__ int sh[1024];
    int t = threadIdx.x;
    sh[t] = (t < NBN) ? g_bsum[t] : 0;
    __syncthreads();
    for (int off = 1; off < 1024; off <<= 1) {
        int v = (t >= off) ? sh[t - off] : 0;
        __syncthreads();
        sh[t] += v;
        __syncthreads();
    }
    if (t < NBN) g_bofs[t] = sh[t] - g_bsum[t];
    __syncthreads();
    int c = (t < NG) ? g_cnt[t] : 0;
    sh[t] = c;
    __syncthreads();
    for (int off = 1; off < 1024; off <<= 1) {
        int v = (t >= off) ? sh[t - off] : 0;
        __syncthreads();
        sh[t] += v;
        __syncthreads();
    }
    if (t < NG) g_start[t] = sh[t] - c;
}

__global__ void k_rowfill() {
    __shared__ int sh[256];
    int t = threadIdx.x;
    int i = blockIdx.x * 256 + t;
    int d = (i < NN) ? g_deg[i] : 0;
    sh[t] = d;
    __syncthreads();
    for (int off = 1; off < 256; off <<= 1) {
        int v = (t >= off) ? sh[t - off] : 0;
        __syncthreads();
        sh[t] += v;
        __syncthreads();
    }
    if (i < NN) {
        int rs = g_bofs[blockIdx.x] + sh[t] - d;
        g_rowstart[i] = rs;
        g_cursor[i]   = rs;
    }
}

__global__ void k_fill(const int* __restrict__ ei) {
    int e = blockIdx.x * blockDim.x + threadIdx.x;
    if (e >= NE) return;
    int s = __ldg(&ei[e]), d = __ldg(&ei[NE + e]);
    if (s == d) return;
    float c = g_invsqrt[s] * g_invsqrt[d];
    int pos = atomicAdd(&g_cursor[d], 1);
    g_epack[pos] = ((long long)__float_as_int(c) << 32) | (unsigned int)s;
}

// ---------------- GEMM layer1: hw = x @ W1 (128 -> 32) ----------------
__global__ void k_gemm128(const float* __restrict__ h, const float* __restrict__ W,
                          float* __restrict__ hw) {
    __shared__ float sW[128 * 32];
    for (int i = threadIdx.x; i < 128 * 32; i += blockDim.x) sW[i] = W[i];
    __syncthreads();
    int node = blockIdx.x * blockDim.x + threadIdx.x;
    if (node >= NN) return;
    float acc[32];
#pragma unroll
    for (int j = 0; j < 32; j++) acc[j] = 0.f;
    const float4* hr = (const float4*)(h + (size_t)node * 128);
#pragma unroll 4
    for (int k4 = 0; k4 < 32; k4++) {
        float4 v = hr[k4];
        const float* hk = &v.x;
#pragma unroll
        for (int kk = 0; kk < 4; kk++) {
            float hv = hk[kk];
            const float4* wr = (const float4*)&sW[(k4 * 4 + kk) * 32];
#pragma unroll
            for (int q = 0; q < 8; q++) {
                float4 w = wr[q];
                acc[4 * q]     += hv * w.x;
                acc[4 * q + 1] += hv * w.y;
                acc[4 * q + 2] += hv * w.z;
                acc[4 * q + 3] += hv * w.w;
            }
        }
    }
    float4* hwv = (float4*)(hw + (size_t)node * 32);
#pragma unroll
    for (int q = 0; q < 8; q++) {
        float4 a;
        a.x = acc[4 * q]; a.y = acc[4 * q + 1]; a.z = acc[4 * q + 2]; a.w = acc[4 * q + 3];
        hwv[q] = a;
    }
}

// layer 4 projection: hw4 = h @ W4   (32 -> 1)
__global__ void k_gemm_c1(const float* __restrict__ h, const float* __restrict__ W) {
    __shared__ float sW[32];
    if (threadIdx.x < 32) sW[threadIdx.x] = W[threadIdx.x];
    __syncthreads();
    int node = blockIdx.x * blockDim.x + threadIdx.x;
    if (node >= NN) return;
    const float4* hr = (const float4*)(h + (size_t)node * 32);
    float acc = 0.f;
#pragma unroll
    for (int q = 0; q < 8; q++) {
        float4 v = hr[q];
        acc += v.x * sW[4 * q] + v.y * sW[4 * q + 1] + v.z * sW[4 * q + 2] + v.w * sW[4 * q + 3];
    }
    g_hw4[node] = acc;
}

// ---- 4-edge x float4 aggregation core: returns agg+self*invdeg for this
//      lane's channel quad (q = lane&7), replicated across the 4 groups. ----
__device__ __forceinline__ float4 agg_quad(const float* __restrict__ in, int node,
                                           int g, int q) {
    int rs = g_rowstart[node];
    int deg = g_deg[node];
    int re = rs + deg;
    float4 acc = make_float4(0.f, 0.f, 0.f, 0.f);
    int e = rs;
    for (; e + 4 <= re; e += 4) {
        long long p = __ldg(&g_epack[e + g]);
        int   s = (int)(p & 0xffffffffLL);
        float c = __int_as_float((int)(p >> 32));
        float4 v = __ldg((const float4*)(in + (size_t)s * 32 + q * 4));
        acc.x += v.x * c; acc.y += v.y * c; acc.z += v.z * c; acc.w += v.w * c;
    }
    int rem = re - e;
    if (g < rem) {
        long long p = __ldg(&g_epack[e + g]);
        int   s = (int)(p & 0xffffffffLL);
        float c = __int_as_float((int)(p >> 32));
        float4 v = __ldg((const float4*)(in + (size_t)s * 32 + q * 4));
        acc.x += v.x * c; acc.y += v.y * c; acc.z += v.z * c; acc.w += v.w * c;
    }
    // reduce across the 4 edge-groups (lanes l, l^8, l^16, l^24)
#pragma unroll
    for (int off = 8; off <= 16; off <<= 1) {
        acc.x += __shfl_xor_sync(FULLM, acc.x, off);
        acc.y += __shfl_xor_sync(FULLM, acc.y, off);
        acc.z += __shfl_xor_sync(FULLM, acc.z, off);
        acc.w += __shfl_xor_sync(FULLM, acc.w, off);
    }
    // self loop (all replicas compute identically)
    float idg = g_invdeg[node];
    float4 self = __ldg((const float4*)(in + (size_t)node * 32 + q * 4));
    acc.x += self.x * idg; acc.y += self.y * idg;
    acc.z += self.z * idg; acc.w += self.w * idg;
    return acc;
}

// ---------------- layer-1 gather: x1 = tanh(agg(hw) + hw*invdeg + b) ----------
__global__ void k_gather_q(const float* __restrict__ in, float* __restrict__ out,
                           const float* __restrict__ b) {
    int w = (blockIdx.x * blockDim.x + threadIdx.x) >> 5;
    if (w >= NN) return;
    int lane = threadIdx.x & 31;
    int g = lane >> 3, q = lane & 7;
    float4 acc = agg_quad(in, w, g, q);
    if (g == 0) {
        float4 bb = __ldg((const float4*)(b + q * 4));
        float4 o;
        o.x = tanhf(acc.x + bb.x); o.y = tanhf(acc.y + bb.y);
        o.z = tanhf(acc.z + bb.z); o.w = tanhf(acc.w + bb.w);
        *((float4*)(out + (size_t)w * 32 + q * 4)) = o;
    }
}

// ---------------- fused gather+GEMM (layers 2,3): out = tanh(A @ W + b) -------
__global__ void __launch_bounds__(256) k_gathergemm(
    const float* __restrict__ in, const float* __restrict__ W,
    const float* __restrict__ b, float* __restrict__ out, int nwarps) {
    int lane = threadIdx.x & 31;
    int wid  = (blockIdx.x * blockDim.x + threadIdx.x) >> 5;
    int g = lane >> 3, q = lane & 7;
    // preload W column `lane` and bias (amortized over grid-stride nodes)
    float Wc[32];
#pragma unroll
    for (int c = 0; c < 32; c++) Wc[c] = __ldg(&W[c * 32 + lane]);
    float bias = __ldg(&b[lane]);

    for (int node = wid; node < NN; node += nwarps) {
        float4 acc = agg_quad(in, node, g, q);
        float o = bias;
#pragma unroll
        for (int c = 0; c < 32; c++) {
            float comp = ((c & 3) == 0) ? acc.x : ((c & 3) == 1) ? acc.y :
                         ((c & 3) == 2) ? acc.z : acc.w;
            float v = __shfl_sync(FULLM, comp, c >> 2);
            o += v * Wc[c];
        }
        out[(size_t)node * 32 + lane] = tanhf(o);
    }
}

// ---------------- layer-4 gather (scalar) ----------------
__global__ void k_gather1(const float* __restrict__ b4) {
    int node = blockIdx.x * blockDim.x + threadIdx.x;
    if (node >= NN) return;
    int rs = g_rowstart[node];
    int re = rs + g_deg[node];
    float acc = g_hw4[node] * g_invdeg[node] + __ldg(&b4[0]);
    int e = rs;
    for (; e + 4 <= re; e += 4) {
        long long p0 = __ldg(&g_epack[e]);
        long long p1 = __ldg(&g_epack[e + 1]);
        long long p2 = __ldg(&g_epack[e + 2]);
        long long p3 = __ldg(&g_epack[e + 3]);
        acc += g_hw4[(int)(p0 & 0xffffffffLL)] * __int_as_float((int)(p0 >> 32));
        acc += g_hw4[(int)(p1 & 0xffffffffLL)] * __int_as_float((int)(p1 >> 32));
        acc += g_hw4[(int)(p2 & 0xffffffffLL)] * __int_as_float((int)(p2 >> 32));
        acc += g_hw4[(int)(p3 & 0xffffffffLL)] * __int_as_float((int)(p3 >> 32));
    }
    for (; e < re; e++) {
        long long p = __ldg(&g_epack[e]);
        acc += g_hw4[(int)(p & 0xffffffffLL)] * __int_as_float((int)(p >> 32));
    }
    g_x4[node] = tanhf(acc);
}

// ---------------- sort-pool + CNN/FC head ----------------
__global__ void __launch_bounds__(128) k_head(
    const float* __restrict__ w5, const float* __restrict__ b5,
    const float* __restrict__ w6, const float* __restrict__ b6,
    const float* __restrict__ fw1, const float* __restrict__ fb1,
    const float* __restrict__ fw2, const float* __restrict__ fb2,
    float* __restrict__ out) {
    const int T = 128;
    int g = blockIdx.x;
    int tid = threadIdx.x;

    __shared__ unsigned long long keys[MAXSORT];
    __shared__ float pooled[KP * CC];
    __shared__ float z5[16 * 30];
    __shared__ float p5[16 * 15];
    __shared__ float z6[352];
    __shared__ float h1[128];
    __shared__ float logits[10];
    __shared__ int   seln[KP];
    __shared__ float bestv[128];
    __shared__ int   besti[128];

    int start = g_start[g];
    int cnt   = g_cnt[g];
    int kk = cnt < KP ? cnt : KP;

    for (int i = tid; i < KP * CC; i += T) pooled[i] = 0.f;

    if (cnt <= MAXSORT) {
        int n2 = 1;
        while (n2 < cnt) n2 <<= 1;
        for (int i = tid; i < n2; i += T) {
            if (i < cnt) {
                unsigned u = __float_as_uint(g_x4[start + i]);
                u ^= (u >> 31) ? 0xFFFFFFFFu : 0x80000000u;
                u = ~u;
                keys[i] = ((unsigned long long)u << 32) | (unsigned)(start + i);
            } else {
                keys[i] = 0xFFFFFFFFFFFFFFFFull;
            }
        }
        __syncthreads();
        for (int k = 2; k <= n2; k <<= 1) {
            for (int j = k >> 1; j > 0; j >>= 1) {
                for (int i = tid; i < n2; i += T) {
                    int ixj = i ^ j;
                    if (ixj > i) {
                        bool up = ((i & k) == 0);
                        unsigned long long a = keys[i], bk = keys[ixj];
                        if ((a > bk) == up) { keys[i] = bk; keys[ixj] = a; }
                    }
                }
                __syncthreads();
            }
        }
        for (int r = tid; r < kk; r += T)
            seln[r] = (int)(keys[r] & 0xffffffffull);
        __syncthreads();
    } else {
        __shared__ float pv_s;
        __shared__ int pidx_s;
        if (tid == 0) { pv_s = 3.0e38f; pidx_s = -1; }
        __syncthreads();
        for (int r = 0; r < kk; r++) {
            float lpv = pv_s; int lpidx = pidx_s;
            float bv = -3.0e38f; int bi = 0x7fffffff;
            for (int i = start + tid; i < start + cnt; i += T) {
                float v = g_x4[i];
                bool after = (v < lpv) || (v == lpv && i > lpidx);
                if (after && ((v > bv) || (v == bv && i < bi))) { bv = v; bi = i; }
            }
            bestv[tid] = bv; besti[tid] = bi;
            __syncthreads();
            for (int sft = T / 2; sft > 0; sft >>= 1) {
                if (tid < sft) {
                    float ov = bestv[tid + sft]; int oi = besti[tid + sft];
                    if ((ov > bestv[tid]) || (ov == bestv[tid] && oi < besti[tid])) {
                        bestv[tid] = ov; besti[tid] = oi;
                    }
                }
                __syncthreads();
            }
            if (tid == 0) { seln[r] = besti[0]; pv_s = bestv[0]; pidx_s = besti[0]; }
            __syncthreads();
        }
    }

    for (int idx = tid; idx < kk * CC; idx += T) {
        int r = idx / CC, c = idx % CC;
        int node = seln[r];
        float val;
        if (c < 32)      val = g_x1[(size_t)node * 32 + c];
        else if (c < 64) val = g_x2[(size_t)node * 32 + (c - 32)];
        else if (c < 96) val = g_x3[(size_t)node * 32 + (c - 64)];
        else             val = g_x4[node];
        pooled[r * CC + c] = val;
    }
    __syncthreads();

    for (int idx = tid; idx < 16 * 30; idx += T) {
        int oc = idx / 30, t = idx % 30;
        float s = b5[oc];
        const float* wr = &w5[oc * 97];
        const float* pr = &pooled[t * 97];
        for (int c = 0; c < 97; c++) s += pr[c] * wr[c];
        z5[oc * 30 + t] = fmaxf(s, 0.f);
    }
    __syncthreads();
    for (int idx = tid; idx < 16 * 15; idx += T) {
        int oc = idx / 15, u = idx % 15;
        p5[idx] = fmaxf(z5[oc * 30 + 2 * u], z5[oc * 30 + 2 * u + 1]);
    }
    __syncthreads();
    for (int idx = tid; idx < 352; idx += T) {
        int oc = idx / 11, v = idx % 11;
        float s = b6[oc];
        for (int ic = 0; ic < 16; ic++) {
            const float* wr = &w6[oc * 80 + ic * 5];
            const float* pr = &p5[ic * 15 + v];
#pragma unroll
            for (int qq = 0; qq < 5; qq++) s += pr[qq] * wr[qq];
        }
        z6[idx] = fmaxf(s, 0.f);
    }
    __syncthreads();
    for (int j = tid; j < 128; j += T) {
        float s = fb1[j];
        for (int i = 0; i < 352; i++) s += z6[i] * fw1[i * 128 + j];
        h1[j] = fmaxf(s, 0.f);
    }
    __syncthreads();
    for (int c = tid; c < 10; c += T) {
        float s = fb2[c];
        for (int j = 0; j < 128; j++) s += h1[j] * fw2[j * 10 + c];
        logits[c] = s;
    }
    __syncthreads();
    if (tid == 0) {
        float mx = logits[0];
        for (int c = 1; c < 10; c++) mx = fmaxf(mx, logits[c]);
        float se = 0.f;
        for (int c = 0; c < 10; c++) se += expf(logits[c] - mx);
        float lse = logf(se) + mx;
        for (int c = 0; c < 10; c++) out[(size_t)g * 10 + c] = logits[c] - lse;
    }
}

// ---------------- launch ----------------
extern "C" void kernel_launch(void* const* d_in, const int* in_sizes, int n_in,
                              void* d_out, int out_size) {
    const float* x      = (const float*)d_in[0];
    const int*   ei     = (const int*)d_in[1];
    const int*   batch  = (const int*)d_in[2];
    const float* W1 = (const float*)d_in[3];  const float* b1 = (const float*)d_in[4];
    const float* W2 = (const float*)d_in[5];  const float* b2 = (const float*)d_in[6];
    const float* W3 = (const float*)d_in[7];  const float* b3 = (const float*)d_in[8];
    const float* W4 = (const float*)d_in[9];  const float* b4 = (const float*)d_in[10];
    const float* w5 = (const float*)d_in[11]; const float* b5 = (const float*)d_in[12];
    const float* w6 = (const float*)d_in[13]; const float* b6 = (const float*)d_in[14];
    const float* fw1 = (const float*)d_in[15]; const float* fb1 = (const float*)d_in[16];
    const float* fw2 = (const float*)d_in[17]; const float* fb2 = (const float*)d_in[18];
    float* out = (float*)d_out;

    void *p_hw, *p_x1, *p_x2, *p_x3;
    cudaGetSymbolAddress(&p_hw, g_hw);
    cudaGetSymbolAddress(&p_x1, g_x1);
    cudaGetSymbolAddress(&p_x2, g_x2);
    cudaGetSymbolAddress(&p_x3, g_x3);
    float* hw = (float*)p_hw;
    float* x1 = (float*)p_x1;
    float* x2 = (float*)p_x2;
    float* x3 = (float*)p_x3;

    const int TB = 256;
    const int NB_N = NBN;                         // 782
    const int NB_E = (NE + TB - 1) / TB;
    const int NB_W = (NN * 32 + TB - 1) / TB;     // warp-per-node
    const int GG_BLOCKS = 1184;                   // 8 blocks/SM * 148
    const int GG_WARPS  = GG_BLOCKS * (TB / 32);

    // CSR + normalization preprocessing
    k_init<<<NB_N, TB>>>();
    k_degcnt<<<NB_E, TB>>>(ei, batch);
    k_prep<<<NB_N, TB>>>();
    k_scan1<<<1, 1024>>>();
    k_rowfill<<<NB_N, TB>>>();
    k_fill<<<NB_E, TB>>>(ei);

    // layer 1: 128 -> 32 (separate GEMM keeps edge traffic at 32ch)
    k_gemm128<<<NB_N, TB>>>(x, W1, hw);
    k_gather_q<<<NB_W, TB>>>(hw, x1, b1);
    // layers 2,3: fused gather+GEMM
    k_gathergemm<<<GG_BLOCKS, TB>>>(x1, W2, b2, x2, GG_WARPS);
    k_gathergemm<<<GG_BLOCKS, TB>>>(x2, W3, b3, x3, GG_WARPS);
    // layer 4: 32 -> 1
    k_gemm_c1<<<NB_N, TB>>>(x3, W4);
    k_gather1<<<NB_N, TB>>>(b4);

    // sort-pool + head
    k_head<<<NG, 128>>>(w5, b5, w6, b6, fw1, fb1, fw2, fb2, out);
}

// round 6
// speedup vs baseline: 2.0593x; 1.0760x over previous
#include <cuda_runtime.h>
#include <math.h>

#define NN 200000
#define NE 3200000
#define NG 1000
#define KP 30
#define CC 97
#define NBN 782            // ceil(NN/256)
#define MAXSORT 2048
#define FULLM 0xffffffffu

typedef unsigned long long ull;

// ---------------- device scratch ----------------
__device__ int   g_deg[NN];
__device__ float g_invsqrt[NN];
__device__ float g_sqrtdeg[NN];
__device__ int   g_bsum[NBN];
__device__ int   g_bofs[NBN];
__device__ int   g_rowstart[NN];
__device__ int   g_cursor[NN];
__device__ int   g_esrc[NE];             // CSR payload: src index only
__device__ __align__(16) float g_hw[NN * 32];   // premultiplied rows
__device__ __align__(16) float g_hw4[NN];
__device__ __align__(16) float g_x1[NN * 32];   // premultiplied tanh outputs
__device__ __align__(16) float g_x2[NN * 32];
__device__ __align__(16) float g_x3[NN * 32];
__device__ __align__(16) float g_x4[NN];        // raw (final layer)
__device__ int g_cnt[NG];
__device__ int g_start[NG];

// ---------------- fp32x2 packed math ----------------
__device__ __forceinline__ ull pk2(float a, float b) {
    ull r;
    asm("mov.b64 %0, {%1, %2};" : "=l"(r) : "f"(a), "f"(b));
    return r;
}
__device__ __forceinline__ ull ffma2(ull a, ull b, ull c) {
    ull d;
    asm("fma.rn.f32x2 %0, %1, %2, %3;" : "=l"(d) : "l"(a), "l"(b), "l"(c));
    return d;
}
__device__ __forceinline__ float2 upk2(ull a) {
    float x, y;
    asm("mov.b64 {%0, %1}, %2;" : "=f"(x), "=f"(y) : "l"(a));
    return make_float2(x, y);
}

// ---------------- preprocessing ----------------
__global__ void k_init() {
    int i = blockIdx.x * blockDim.x + threadIdx.x;
    if (i < NN) g_deg[i] = 0;
    if (i < NG) g_cnt[i] = 0;
}

__global__ void k_degcnt(const int* __restrict__ ei, const int* __restrict__ batch) {
    int i = blockIdx.x * blockDim.x + threadIdx.x;
    int e4 = i * 4;
    if (e4 < NE) {
        int4 s = __ldg((const int4*)(ei + e4));
        int4 d = __ldg((const int4*)(ei + NE + e4));
        if (s.x != d.x) atomicAdd(&g_deg[d.x], 1);
        if (s.y != d.y) atomicAdd(&g_deg[d.y], 1);
        if (s.z != d.z) atomicAdd(&g_deg[d.z], 1);
        if (s.w != d.w) atomicAdd(&g_deg[d.w], 1);
    }
    if (i < NN) atomicAdd(&g_cnt[batch[i]], 1);
}

__global__ void k_prep() {
    __shared__ int ssum[256];
    int t = threadIdx.x;
    int i = blockIdx.x * 256 + t;
    int d = 0;
    if (i < NN) {
        d = g_deg[i];
        float dg = (float)d + 1.0f;
        float is = rsqrtf(dg);
        g_invsqrt[i] = is;
        g_sqrtdeg[i] = dg * is;
    }
    ssum[t] = d;
    __syncthreads();
    for (int s = 128; s > 0; s >>= 1) {
        if (t < s) ssum[t] += ssum[t + s];
        __syncthreads();
    }
    if (t == 0) g_bsum[blockIdx.x] = ssum[0];
}

__global__ void k_scan1() {
    __shared__ int sh[1024];
    int t = threadIdx.x;
    sh[t] = (t < NBN) ? g_bsum[t] : 0;
    __syncthreads();
    for (int off = 1; off < 1024; off <<= 1) {
        int v = (t >= off) ? sh[t - off] : 0;
        __syncthreads();
        sh[t] += v;
        __syncthreads();
    }
    if (t < NBN) g_bofs[t] = sh[t] - g_bsum[t];
    __syncthreads();
    int c = (t < NG) ? g_cnt[t] : 0;
    sh[t] = c;
    __syncthreads();
    for (int off = 1; off < 1024; off <<= 1) {
        int v = (t >= off) ? sh[t - off] : 0;
        __syncthreads();
        sh[t] += v;
        __syncthreads();
    }
    if (t < NG) g_start[t] = sh[t] - c;
}

__global__ void k_rowfill() {
    __shared__ int sh[256];
    int t = threadIdx.x;
    int i = blockIdx.x * 256 + t;
    int d = (i < NN) ? g_deg[i] : 0;
    sh[t] = d;
    __syncthreads();
    for (int off = 1; off < 256; off <<= 1) {
        int v = (t >= off) ? sh[t - off] : 0;
        __syncthreads();
        sh[t] += v;
        __syncthreads();
    }
    if (i < NN) {
        int rs = g_bofs[blockIdx.x] + sh[t] - d;
        g_rowstart[i] = rs;
        g_cursor[i]   = rs;
    }
}

__global__ void k_fill(const int* __restrict__ ei) {
    int i = blockIdx.x * blockDim.x + threadIdx.x;
    int e4 = i * 4;
    if (e4 >= NE) return;
    int4 s = __ldg((const int4*)(ei + e4));
    int4 d = __ldg((const int4*)(ei + NE + e4));
    if (s.x != d.x) g_esrc[atomicAdd(&g_cursor[d.x], 1)] = s.x;
    if (s.y != d.y) g_esrc[atomicAdd(&g_cursor[d.y], 1)] = s.y;
    if (s.z != d.z) g_esrc[atomicAdd(&g_cursor[d.z], 1)] = s.z;
    if (s.w != d.w) g_esrc[atomicAdd(&g_cursor[d.w], 1)] = s.w;
}

// ---------------- GEMM layer1: hws = (x @ W1) * invsqrt  (128 -> 32) ----------
__global__ void k_gemm128(const float* __restrict__ h, const float* __restrict__ W,
                          float* __restrict__ hw) {
    __shared__ float sW[128 * 32];
    for (int i = threadIdx.x; i < 128 * 32; i += blockDim.x) sW[i] = W[i];
    __syncthreads();
    int node = blockIdx.x * blockDim.x + threadIdx.x;
    if (node >= NN) return;
    ull acc[16];
#pragma unroll
    for (int j = 0; j < 16; j++) acc[j] = 0ull;
    const float4* hr = (const float4*)(h + (size_t)node * 128);
#pragma unroll 4
    for (int k4 = 0; k4 < 32; k4++) {
        float4 v = hr[k4];
        const float* hk = &v.x;
#pragma unroll
        for (int kk = 0; kk < 4; kk++) {
            ull hv2 = pk2(hk[kk], hk[kk]);
            const float4* wr = (const float4*)&sW[(k4 * 4 + kk) * 32];
#pragma unroll
            for (int q = 0; q < 8; q++) {
                float4 w = wr[q];
                acc[2 * q]     = ffma2(hv2, pk2(w.x, w.y), acc[2 * q]);
                acc[2 * q + 1] = ffma2(hv2, pk2(w.z, w.w), acc[2 * q + 1]);
            }
        }
    }
    float isq = g_invsqrt[node];
    float4* hwv = (float4*)(hw + (size_t)node * 32);
#pragma unroll
    for (int q = 0; q < 8; q++) {
        float2 a = upk2(acc[2 * q]);
        float2 bq = upk2(acc[2 * q + 1]);
        float4 o;
        o.x = a.x * isq; o.y = a.y * isq; o.z = bq.x * isq; o.w = bq.y * isq;
        hwv[q] = o;
    }
}

// layer 4 projection: w4s[node] = y3[node] . W4  (premultiplied dot)
__global__ void k_gemm_c1(const float* __restrict__ h, const float* __restrict__ W) {
    __shared__ float sW[32];
    if (threadIdx.x < 32) sW[threadIdx.x] = W[threadIdx.x];
    __syncthreads();
    int node = blockIdx.x * blockDim.x + threadIdx.x;
    if (node >= NN) return;
    const float4* hr = (const float4*)(h + (size_t)node * 32);
    float acc = 0.f;
#pragma unroll
    for (int q = 0; q < 8; q++) {
        float4 v = hr[q];
        acc += v.x * sW[4 * q] + v.y * sW[4 * q + 1] + v.z * sW[4 * q + 2] + v.w * sW[4 * q + 3];
    }
    g_hw4[node] = acc;
}

// ---- 4-edge x float4 plain-sum aggregation (incl. self row), MLP=8 unroll ----
// lane layout: g = lane>>3 (edge group), q = lane&7 (channel quad)
__device__ __forceinline__ float4 agg_sum(const float* __restrict__ in, int node,
                                          int g, int q) {
    int rs = g_rowstart[node];
    int re = rs + g_deg[node];
    float4 acc = __ldg((const float4*)(in + (size_t)node * 32 + q * 4)); // self
    if (g != 0) acc = make_float4(0.f, 0.f, 0.f, 0.f);
    int e = rs;
    for (; e + 8 <= re; e += 8) {
        int s0 = __ldg(&g_esrc[e + g]);
        int s1 = __ldg(&g_esrc[e + 4 + g]);
        float4 v0 = __ldg((const float4*)(in + (size_t)s0 * 32 + q * 4));
        float4 v1 = __ldg((const float4*)(in + (size_t)s1 * 32 + q * 4));
        acc.x += v0.x + v1.x; acc.y += v0.y + v1.y;
        acc.z += v0.z + v1.z; acc.w += v0.w + v1.w;
    }
    if (e + 4 <= re) {
        int s0 = __ldg(&g_esrc[e + g]);
        float4 v0 = __ldg((const float4*)(in + (size_t)s0 * 32 + q * 4));
        acc.x += v0.x; acc.y += v0.y; acc.z += v0.z; acc.w += v0.w;
        e += 4;
    }
    int rem = re - e;
    if (g < rem) {
        int s0 = __ldg(&g_esrc[e + g]);
        float4 v0 = __ldg((const float4*)(in + (size_t)s0 * 32 + q * 4));
        acc.x += v0.x; acc.y += v0.y; acc.z += v0.z; acc.w += v0.w;
    }
#pragma unroll
    for (int off = 8; off <= 16; off <<= 1) {
        acc.x += __shfl_xor_sync(FULLM, acc.x, off);
        acc.y += __shfl_xor_sync(FULLM, acc.y, off);
        acc.z += __shfl_xor_sync(FULLM, acc.z, off);
        acc.w += __shfl_xor_sync(FULLM, acc.w, off);
    }
    return acc;
}

// ---------------- layer-1 gather: y1 = tanh(isq*acc + b) * isq ----------------
__global__ void __launch_bounds__(256) k_gather_q(
    const float* __restrict__ in, float* __restrict__ out,
    const float* __restrict__ b, int nwarps) {
    int lane = threadIdx.x & 31;
    int wid  = (blockIdx.x * blockDim.x + threadIdx.x) >> 5;
    int g = lane >> 3, q = lane & 7;
    float4 bb = __ldg((const float4*)(b + q * 4));
    for (int node = wid; node < NN; node += nwarps) {
        float4 acc = agg_sum(in, node, g, q);
        if (g == 0) {
            float isq = g_invsqrt[node];
            float4 o;
            o.x = tanhf(acc.x * isq + bb.x) * isq;
            o.y = tanhf(acc.y * isq + bb.y) * isq;
            o.z = tanhf(acc.z * isq + bb.z) * isq;
            o.w = tanhf(acc.w * isq + bb.w) * isq;
            *((float4*)(out + (size_t)node * 32 + q * 4)) = o;
        }
    }
}

// ------------- fused gather+GEMM (layers 2,3): y = tanh((isq*acc)@W + b)*isq ---
__global__ void __launch_bounds__(256) k_gathergemm(
    const float* __restrict__ in, const float* __restrict__ W,
    const float* __restrict__ b, float* __restrict__ out, int nwarps) {
    int lane = threadIdx.x & 31;
    int wid  = (blockIdx.x * blockDim.x + threadIdx.x) >> 5;
    int g = lane >> 3, q = lane & 7;
    ull Wp[16];
#pragma unroll
    for (int c = 0; c < 16; c++)
        Wp[c] = pk2(__ldg(&W[(2 * c) * 32 + lane]), __ldg(&W[(2 * c + 1) * 32 + lane]));
    float bias = __ldg(&b[lane]);

    for (int node = wid; node < NN; node += nwarps) {
        float4 acc = agg_sum(in, node, g, q);
        float isq = g_invsqrt[node];
        acc.x *= isq; acc.y *= isq; acc.z *= isq; acc.w *= isq;
        ull o2 = pk2(bias, 0.f);
#pragma unroll
        for (int c = 0; c < 32; c += 2) {
            float va, vb;
            {
                float comp = ((c & 3) == 0) ? acc.x : ((c & 3) == 1) ? acc.y :
                             ((c & 3) == 2) ? acc.z : acc.w;
                va = __shfl_sync(FULLM, comp, c >> 2);
            }
            {
                int c1 = c + 1;
                float comp = ((c1 & 3) == 0) ? acc.x : ((c1 & 3) == 1) ? acc.y :
                             ((c1 & 3) == 2) ? acc.z : acc.w;
                vb = __shfl_sync(FULLM, comp, c1 >> 2);
            }
            o2 = ffma2(pk2(va, vb), Wp[c >> 1], o2);
        }
        float2 oo = upk2(o2);
        out[(size_t)node * 32 + lane] = tanhf(oo.x + oo.y) * isq;
    }
}

// ---------------- layer-4 gather (scalar): x4 = tanh(isq*acc + b4) ------------
__global__ void k_gather1(const float* __restrict__ b4) {
    int node = blockIdx.x * blockDim.x + threadIdx.x;
    if (node >= NN) return;
    int rs = g_rowstart[node];
    int re = rs + g_deg[node];
    float acc = g_hw4[node];   // self
    int e = rs;
    for (; e + 4 <= re; e += 4) {
        int s0 = __ldg(&g_esrc[e]);
        int s1 = __ldg(&g_esrc[e + 1]);
        int s2 = __ldg(&g_esrc[e + 2]);
        int s3 = __ldg(&g_esrc[e + 3]);
        acc += g_hw4[s0] + g_hw4[s1] + g_hw4[s2] + g_hw4[s3];
    }
    for (; e < re; e++) acc += g_hw4[__ldg(&g_esrc[e])];
    g_x4[node] = tanhf(acc * g_invsqrt[node] + __ldg(&b4[0]));
}

// ---------------- sort-pool + CNN/FC head ----------------
__global__ void __launch_bounds__(128) k_head(
    const float* __restrict__ w5, const float* __restrict__ b5,
    const float* __restrict__ w6, const float* __restrict__ b6,
    const float* __restrict__ fw1, const float* __restrict__ fb1,
    const float* __restrict__ fw2, const float* __restrict__ fb2,
    float* __restrict__ out) {
    const int T = 128;
    int g = blockIdx.x;
    int tid = threadIdx.x;

    __shared__ unsigned long long keys[MAXSORT];
    __shared__ float pooled[KP * CC];
    __shared__ float z5[16 * 30];
    __shared__ float p5[16 * 15];
    __shared__ float z6[352];
    __shared__ float h1[128];
    __shared__ float logits[10];
    __shared__ int   seln[KP];
    __shared__ float bestv[128];
    __shared__ int   besti[128];

    int start = g_start[g];
    int cnt   = g_cnt[g];
    int kk = cnt < KP ? cnt : KP;

    for (int i = tid; i < KP * CC; i += T) pooled[i] = 0.f;

    if (cnt <= MAXSORT) {
        int n2 = 1;
        while (n2 < cnt) n2 <<= 1;
        for (int i = tid; i < n2; i += T) {
            if (i < cnt) {
                unsigned u = __float_as_uint(g_x4[start + i]);
                u ^= (u >> 31) ? 0xFFFFFFFFu : 0x80000000u;
                u = ~u;
                keys[i] = ((unsigned long long)u << 32) | (unsigned)(start + i);
            } else {
                keys[i] = 0xFFFFFFFFFFFFFFFFull;
            }
        }
        __syncthreads();
        for (int k = 2; k <= n2; k <<= 1) {
            for (int j = k >> 1; j > 0; j >>= 1) {
                for (int i = tid; i < n2; i += T) {
                    int ixj = i ^ j;
                    if (ixj > i) {
                        bool up = ((i & k) == 0);
                        unsigned long long a = keys[i], bk = keys[ixj];
                        if ((a > bk) == up) { keys[i] = bk; keys[ixj] = a; }
                    }
                }
                __syncthreads();
            }
        }
        for (int r = tid; r < kk; r += T)
            seln[r] = (int)(keys[r] & 0xffffffffull);
        __syncthreads();
    } else {
        __shared__ float pv_s;
        __shared__ int pidx_s;
        if (tid == 0) { pv_s = 3.0e38f; pidx_s = -1; }
        __syncthreads();
        for (int r = 0; r < kk; r++) {
            float lpv = pv_s; int lpidx = pidx_s;
            float bv = -3.0e38f; int bi = 0x7fffffff;
            for (int i = start + tid; i < start + cnt; i += T) {
                float v = g_x4[i];
                bool after = (v < lpv) || (v == lpv && i > lpidx);
                if (after && ((v > bv) || (v == bv && i < bi))) { bv = v; bi = i; }
            }
            bestv[tid] = bv; besti[tid] = bi;
            __syncthreads();
            for (int sft = T / 2; sft > 0; sft >>= 1) {
                if (tid < sft) {
                    float ov = bestv[tid + sft]; int oi = besti[tid + sft];
                    if ((ov > bestv[tid]) || (ov == bestv[tid] && oi < besti[tid])) {
                        bestv[tid] = ov; besti[tid] = oi;
                    }
                }
                __syncthreads();
            }
            if (tid == 0) { seln[r] = besti[0]; pv_s = bestv[0]; pidx_s = besti[0]; }
            __syncthreads();
        }
    }

    // gather pooled rows [kk x 97] (un-premultiply with sqrtdeg)
    for (int idx = tid; idx < kk * CC; idx += T) {
        int r = idx / CC, c = idx % CC;
        int node = seln[r];
        float val;
        if (c < 96) {
            float sq = g_sqrtdeg[node];
            if (c < 32)      val = g_x1[(size_t)node * 32 + c] * sq;
            else if (c < 64) val = g_x2[(size_t)node * 32 + (c - 32)] * sq;
            else             val = g_x3[(size_t)node * 32 + (c - 64)] * sq;
        } else {
            val = g_x4[node];
        }
        pooled[r * CC + c] = val;
    }
    __syncthreads();

    for (int idx = tid; idx < 16 * 30; idx += T) {
        int oc = idx / 30, t = idx % 30;
        float s = b5[oc];
        const float* wr = &w5[oc * 97];
        const float* pr = &pooled[t * 97];
        for (int c = 0; c < 97; c++) s += pr[c] * wr[c];
        z5[oc * 30 + t] = fmaxf(s, 0.f);
    }
    __syncthreads();
    for (int idx = tid; idx < 16 * 15; idx += T) {
        int oc = idx / 15, u = idx % 15;
        p5[idx] = fmaxf(z5[oc * 30 + 2 * u], z5[oc * 30 + 2 * u + 1]);
    }
    __syncthreads();
    for (int idx = tid; idx < 352; idx += T) {
        int oc = idx / 11, v = idx % 11;
        float s = b6[oc];
        for (int ic = 0; ic < 16; ic++) {
            const float* wr = &w6[oc * 80 + ic * 5];
            const float* pr = &p5[ic * 15 + v];
#pragma unroll
            for (int qq = 0; qq < 5; qq++) s += pr[qq] * wr[qq];
        }
        z6[idx] = fmaxf(s, 0.f);
    }
    __syncthreads();
    for (int j = tid; j < 128; j += T) {
        float s = fb1[j];
        for (int i = 0; i < 352; i++) s += z6[i] * fw1[i * 128 + j];
        h1[j] = fmaxf(s, 0.f);
    }
    __syncthreads();
    for (int c = tid; c < 10; c += T) {
        float s = fb2[c];
        for (int j = 0; j < 128; j++) s += h1[j] * fw2[j * 10 + c];
        logits[c] = s;
    }
    __syncthreads();
    if (tid == 0) {
        float mx = logits[0];
        for (int c = 1; c < 10; c++) mx = fmaxf(mx, logits[c]);
        float se = 0.f;
        for (int c = 0; c < 10; c++) se += expf(logits[c] - mx);
        float lse = logf(se) + mx;
        for (int c = 0; c < 10; c++) out[(size_t)g * 10 + c] = logits[c] - lse;
    }
}

// ---------------- launch ----------------
extern "C" void kernel_launch(void* const* d_in, const int* in_sizes, int n_in,
                              void* d_out, int out_size) {
    const float* x      = (const float*)d_in[0];
    const int*   ei     = (const int*)d_in[1];
    const int*   batch  = (const int*)d_in[2];
    const float* W1 = (const float*)d_in[3];  const float* b1 = (const float*)d_in[4];
    const float* W2 = (const float*)d_in[5];  const float* b2 = (const float*)d_in[6];
    const float* W3 = (const float*)d_in[7];  const float* b3 = (const float*)d_in[8];
    const float* W4 = (const float*)d_in[9];  const float* b4 = (const float*)d_in[10];
    const float* w5 = (const float*)d_in[11]; const float* b5 = (const float*)d_in[12];
    const float* w6 = (const float*)d_in[13]; const float* b6 = (const float*)d_in[14];
    const float* fw1 = (const float*)d_in[15]; const float* fb1 = (const float*)d_in[16];
    const float* fw2 = (const float*)d_in[17]; const float* fb2 = (const float*)d_in[18];
    float* out = (float*)d_out;

    void *p_hw, *p_x1, *p_x2, *p_x3;
    cudaGetSymbolAddress(&p_hw, g_hw);
    cudaGetSymbolAddress(&p_x1, g_x1);
    cudaGetSymbolAddress(&p_x2, g_x2);
    cudaGetSymbolAddress(&p_x3, g_x3);
    float* hw = (float*)p_hw;
    float* x1 = (float*)p_x1;
    float* x2 = (float*)p_x2;
    float* x3 = (float*)p_x3;

    const int TB = 256;
    const int NB_N = NBN;
    const int NB_E4 = (NE / 4 + TB - 1) / TB;     // 3125: covers NE/4 edge quads (and NN)
    const int GG_BLOCKS = 1184;                   // 8 blocks/SM * 148
    const int GG_WARPS  = GG_BLOCKS * (TB / 32);

    k_init<<<NB_N, TB>>>();
    k_degcnt<<<NB_E4, TB>>>(ei, batch);
    k_prep<<<NB_N, TB>>>();
    k_scan1<<<1, 1024>>>();
    k_rowfill<<<NB_N, TB>>>();
    k_fill<<<NB_E4, TB>>>(ei);

    // layer 1: 128 -> 32 (GEMM writes premultiplied rows)
    k_gemm128<<<NB_N, TB>>>(x, W1, hw);
    k_gather_q<<<GG_BLOCKS, TB>>>(hw, x1, b1, GG_WARPS);
    // layers 2,3: fused gather+GEMM
    k_gathergemm<<<GG_BLOCKS, TB>>>(x1, W2, b2, x2, GG_WARPS);
    k_gathergemm<<<GG_BLOCKS, TB>>>(x2, W3, b3, x3, GG_WARPS);
    // layer 4: 32 -> 1
    k_gemm_c1<<<NB_N, TB>>>(x3, W4);
    k_gather1<<<NB_N, TB>>>(b4);

    k_head<<<NG, 128>>>(w5, b5, w6, b6, fw1, fb1, fw2, fb2, out);
}